// round 8
// baseline (speedup 1.0000x reference)
#include <cuda_runtime.h>
#include <cstdint>

#define N_NODES 50000
#define N_EDGES 800000
#define IN_F 256
#define HID 128
#define OUTF 64

// ---------------- scratch (no allocations allowed) ----------------
__device__ int   g_deg_in[N_NODES];
__device__ int   g_deg_out[N_NODES];
__device__ int   g_rowptr[N_NODES];      // exclusive prefix of deg_in
__device__ int   g_blocktot[256];        // scan block totals
__device__ int   g_cursor[N_NODES];      // CSR fill cursors
__device__ int   g_csrc[N_EDGES];        // src node of each dst-grouped edge
__device__ float g_norm_src[N_NODES];
__device__ float g_norm_dst[N_NODES];
__device__ float g_m1[(size_t)N_NODES * HID];   // (x*ns) @ W1
__device__ float g_h[(size_t)N_NODES * HID];    // relu(agg1*nd + b1)
__device__ float g_m2[(size_t)N_NODES * OUTF];  // (h*ns) @ W2

// ---------------- degree counting (int atomics, 50K counters) ----------------
// NOTE: src/dst are int32 (JAX x64 disabled -> jnp.int64 silently becomes int32).
__global__ __launch_bounds__(256) void degree_kernel(
    const int* __restrict__ src, const int* __restrict__ dst,
    int* __restrict__ deg_out, int* __restrict__ deg_in, int E) {
    for (int e = blockIdx.x * blockDim.x + threadIdx.x; e < E;
         e += gridDim.x * blockDim.x) {
        atomicAdd(&deg_out[__ldg(&src[e])], 1);
        atomicAdd(&deg_in[__ldg(&dst[e])], 1);
    }
}

__global__ __launch_bounds__(256) void norm_kernel(
    const int* __restrict__ dout, const int* __restrict__ din,
    float* __restrict__ ns, float* __restrict__ nd, int n) {
    int i = blockIdx.x * blockDim.x + threadIdx.x;
    if (i < n) {
        ns[i] = rsqrtf((float)max(dout[i], 1));
        nd[i] = rsqrtf((float)max(din[i], 1));
    }
}

// ---------------- 3-phase exclusive scan over deg_in -> rowptr ----------------
__global__ __launch_bounds__(256) void scan_phase1(
    const int* __restrict__ deg, int* __restrict__ excl,
    int* __restrict__ btot, int n) {
    __shared__ int sm[256];
    int i = blockIdx.x * 256 + threadIdx.x;
    int v = (i < n) ? deg[i] : 0;
    sm[threadIdx.x] = v;
    __syncthreads();
#pragma unroll
    for (int off = 1; off < 256; off <<= 1) {
        int t = (threadIdx.x >= off) ? sm[threadIdx.x - off] : 0;
        __syncthreads();
        sm[threadIdx.x] += t;
        __syncthreads();
    }
    if (i < n) excl[i] = sm[threadIdx.x] - v;      // exclusive within block
    if (threadIdx.x == 255) btot[blockIdx.x] = sm[255];
}

__global__ __launch_bounds__(256) void scan_phase2(int* __restrict__ btot, int nb) {
    __shared__ int sm[256];
    int v = (threadIdx.x < nb) ? btot[threadIdx.x] : 0;
    sm[threadIdx.x] = v;
    __syncthreads();
#pragma unroll
    for (int off = 1; off < 256; off <<= 1) {
        int t = (threadIdx.x >= off) ? sm[threadIdx.x - off] : 0;
        __syncthreads();
        sm[threadIdx.x] += t;
        __syncthreads();
    }
    if (threadIdx.x < nb) btot[threadIdx.x] = sm[threadIdx.x] - v;  // exclusive
}

__global__ __launch_bounds__(256) void scan_phase3(
    int* __restrict__ excl, const int* __restrict__ btot, int n) {
    int i = blockIdx.x * 256 + threadIdx.x;
    if (i < n) excl[i] += btot[blockIdx.x];
}

// ---------------- CSR fill: group edge srcs by dst ----------------
__global__ __launch_bounds__(256) void csr_fill_kernel(
    const int* __restrict__ src, const int* __restrict__ dst,
    const int* __restrict__ rowptr, int* __restrict__ cursor,
    int* __restrict__ csrc, int E) {
    for (int e = blockIdx.x * blockDim.x + threadIdx.x; e < E;
         e += gridDim.x * blockDim.x) {
        int d = __ldg(&dst[e]);
        int pos = __ldg(&rowptr[d]) + atomicAdd(&cursor[d], 1);
        csrc[pos] = __ldg(&src[e]);
    }
}

// ---------------- row-scaled SGEMM: C[M,BN] = (A .* s[:,None]) @ W[K,BN] ----------------
template <int BM, int BN, int BK, int TM, int TN>
__global__ __launch_bounds__(256) void gemm_rowscale(
    const float* __restrict__ A, const float* __restrict__ s,
    const float* __restrict__ W, float* __restrict__ C, int M, int K) {
    __shared__ float As[BK][BM + 4];
    __shared__ float Ws[BK][BN];

    const int tid = threadIdx.x;
    const int row0 = blockIdx.x * BM;
    constexpr int TX = BN / TN;
    const int tx = tid % TX;
    const int ty = tid / TX;

    float acc[TM][TN];
#pragma unroll
    for (int i = 0; i < TM; i++)
#pragma unroll
        for (int j = 0; j < TN; j++) acc[i][j] = 0.0f;

    constexpr int A_F4 = (BM * BK / 4) / 256;
    constexpr int W_F4 = (BK * BN / 4) / 256;
    constexpr int KC4 = BK / 4;
    constexpr int NC4 = BN / 4;

    for (int k0 = 0; k0 < K; k0 += BK) {
        __syncthreads();
#pragma unroll
        for (int i = 0; i < A_F4; i++) {
            int idx = tid + i * 256;
            int r = idx / KC4;
            int c4 = idx % KC4;
            int grow = row0 + r;
            float4 v = make_float4(0.f, 0.f, 0.f, 0.f);
            float sc = 0.f;
            if (grow < M) {
                v = __ldg((const float4*)(A + (size_t)grow * K + k0 + c4 * 4));
                sc = __ldg(&s[grow]);
            }
            As[c4 * 4 + 0][r] = v.x * sc;
            As[c4 * 4 + 1][r] = v.y * sc;
            As[c4 * 4 + 2][r] = v.z * sc;
            As[c4 * 4 + 3][r] = v.w * sc;
        }
#pragma unroll
        for (int i = 0; i < W_F4; i++) {
            int idx = tid + i * 256;
            int kk = idx / NC4;
            int n4 = idx % NC4;
            float4 v = __ldg((const float4*)(W + (size_t)(k0 + kk) * BN + n4 * 4));
            *(float4*)&Ws[kk][n4 * 4] = v;
        }
        __syncthreads();
#pragma unroll
        for (int k = 0; k < BK; k++) {
            float a[TM], b[TN];
#pragma unroll
            for (int i = 0; i < TM; i += 4) {
                float4 t = *(const float4*)&As[k][ty * TM + i];
                a[i] = t.x; a[i + 1] = t.y; a[i + 2] = t.z; a[i + 3] = t.w;
            }
#pragma unroll
            for (int j = 0; j < TN; j += 4) {
                float4 t = *(const float4*)&Ws[k][tx * TN + j];
                b[j] = t.x; b[j + 1] = t.y; b[j + 2] = t.z; b[j + 3] = t.w;
            }
#pragma unroll
            for (int i = 0; i < TM; i++)
#pragma unroll
                for (int j = 0; j < TN; j++) acc[i][j] += a[i] * b[j];
        }
    }
#pragma unroll
    for (int i = 0; i < TM; i++) {
        int grow = row0 + ty * TM + i;
        if (grow < M) {
#pragma unroll
            for (int j = 0; j < TN; j += 4) {
                float4 v = make_float4(acc[i][j], acc[i][j + 1], acc[i][j + 2], acc[i][j + 3]);
                *(float4*)(C + (size_t)grow * BN + tx * TN + j) = v;
            }
        }
    }
}

// ---------------- gather-side aggregation, fused epilogue ----------------
// One warp per node. F=128: lane owns float4; F=64: lane owns float2.
// out[n] = (RELU?)( sum_{e in in(n)} m[src_e] * nd[n] + bias )
template <bool RELU>
__global__ __launch_bounds__(256) void aggregate128(
    const float* __restrict__ m, const int* __restrict__ rowptr,
    const int* __restrict__ deg, const int* __restrict__ csrc,
    const float* __restrict__ nd, const float* __restrict__ bias,
    float* __restrict__ out, int N) {
    int warp = (blockIdx.x * blockDim.x + threadIdx.x) >> 5;
    int lane = threadIdx.x & 31;
    if (warp >= N) return;
    int start = __ldg(&rowptr[warp]);
    int cnt = __ldg(&deg[warp]);
    float4 acc0 = make_float4(0.f, 0.f, 0.f, 0.f);
    float4 acc1 = make_float4(0.f, 0.f, 0.f, 0.f);
    int j = 0;
    for (; j + 2 <= cnt; j += 2) {
        int s0 = __ldg(&csrc[start + j]);
        int s1 = __ldg(&csrc[start + j + 1]);
        float4 v0 = __ldg((const float4*)(m + (size_t)s0 * 128 + lane * 4));
        float4 v1 = __ldg((const float4*)(m + (size_t)s1 * 128 + lane * 4));
        acc0.x += v0.x; acc0.y += v0.y; acc0.z += v0.z; acc0.w += v0.w;
        acc1.x += v1.x; acc1.y += v1.y; acc1.z += v1.z; acc1.w += v1.w;
    }
    if (j < cnt) {
        int s0 = __ldg(&csrc[start + j]);
        float4 v0 = __ldg((const float4*)(m + (size_t)s0 * 128 + lane * 4));
        acc0.x += v0.x; acc0.y += v0.y; acc0.z += v0.z; acc0.w += v0.w;
    }
    float n = __ldg(&nd[warp]);
    float4 b = __ldg((const float4*)(bias + lane * 4));
    float4 r;
    r.x = (acc0.x + acc1.x) * n + b.x;
    r.y = (acc0.y + acc1.y) * n + b.y;
    r.z = (acc0.z + acc1.z) * n + b.z;
    r.w = (acc0.w + acc1.w) * n + b.w;
    if (RELU) {
        r.x = fmaxf(r.x, 0.f); r.y = fmaxf(r.y, 0.f);
        r.z = fmaxf(r.z, 0.f); r.w = fmaxf(r.w, 0.f);
    }
    *(float4*)(out + (size_t)warp * 128 + lane * 4) = r;
}

template <bool RELU>
__global__ __launch_bounds__(256) void aggregate64(
    const float* __restrict__ m, const int* __restrict__ rowptr,
    const int* __restrict__ deg, const int* __restrict__ csrc,
    const float* __restrict__ nd, const float* __restrict__ bias,
    float* __restrict__ out, int N) {
    int warp = (blockIdx.x * blockDim.x + threadIdx.x) >> 5;
    int lane = threadIdx.x & 31;
    if (warp >= N) return;
    int start = __ldg(&rowptr[warp]);
    int cnt = __ldg(&deg[warp]);
    float2 acc0 = make_float2(0.f, 0.f);
    float2 acc1 = make_float2(0.f, 0.f);
    int j = 0;
    for (; j + 2 <= cnt; j += 2) {
        int s0 = __ldg(&csrc[start + j]);
        int s1 = __ldg(&csrc[start + j + 1]);
        float2 v0 = __ldg((const float2*)(m + (size_t)s0 * 64 + lane * 2));
        float2 v1 = __ldg((const float2*)(m + (size_t)s1 * 64 + lane * 2));
        acc0.x += v0.x; acc0.y += v0.y;
        acc1.x += v1.x; acc1.y += v1.y;
    }
    if (j < cnt) {
        int s0 = __ldg(&csrc[start + j]);
        float2 v0 = __ldg((const float2*)(m + (size_t)s0 * 64 + lane * 2));
        acc0.x += v0.x; acc0.y += v0.y;
    }
    float n = __ldg(&nd[warp]);
    float2 b = __ldg((const float2*)(bias + lane * 2));
    float2 r;
    r.x = (acc0.x + acc1.x) * n + b.x;
    r.y = (acc0.y + acc1.y) * n + b.y;
    if (RELU) { r.x = fmaxf(r.x, 0.f); r.y = fmaxf(r.y, 0.f); }
    *(float2*)(out + (size_t)warp * 64 + lane * 2) = r;
}

// ---------------- launch ----------------
extern "C" void kernel_launch(void* const* d_in, const int* in_sizes, int n_in,
                              void* d_out, int out_size) {
    const float* x = (const float*)d_in[0];
    const int* src = (const int*)d_in[1];   // int32 (JAX x64 disabled)
    const int* dst = (const int*)d_in[2];   // int32
    const float* W1 = (const float*)d_in[3];
    const float* b1 = (const float*)d_in[4];
    const float* W2 = (const float*)d_in[5];
    const float* b2 = (const float*)d_in[6];
    float* out = (float*)d_out;

    int *din, *dout_, *rowptr, *btot, *cursor, *csrc;
    float *ns, *nd, *m1, *h, *m2;
    cudaGetSymbolAddress((void**)&din, g_deg_in);
    cudaGetSymbolAddress((void**)&dout_, g_deg_out);
    cudaGetSymbolAddress((void**)&rowptr, g_rowptr);
    cudaGetSymbolAddress((void**)&btot, g_blocktot);
    cudaGetSymbolAddress((void**)&cursor, g_cursor);
    cudaGetSymbolAddress((void**)&csrc, g_csrc);
    cudaGetSymbolAddress((void**)&ns, g_norm_src);
    cudaGetSymbolAddress((void**)&nd, g_norm_dst);
    cudaGetSymbolAddress((void**)&m1, g_m1);
    cudaGetSymbolAddress((void**)&h, g_h);
    cudaGetSymbolAddress((void**)&m2, g_m2);

    const int NB = (N_NODES + 255) / 256;   // 196

    // Degrees
    cudaMemsetAsync(din, 0, N_NODES * sizeof(int), 0);
    cudaMemsetAsync(dout_, 0, N_NODES * sizeof(int), 0);
    degree_kernel<<<1184, 256>>>(src, dst, dout_, din, N_EDGES);
    // Norms
    norm_kernel<<<NB, 256>>>(dout_, din, ns, nd, N_NODES);
    // rowptr = exclusive_scan(deg_in)
    scan_phase1<<<NB, 256>>>(din, rowptr, btot, N_NODES);
    scan_phase2<<<1, 256>>>(btot, NB);
    scan_phase3<<<NB, 256>>>(rowptr, btot, N_NODES);
    // CSR fill
    cudaMemsetAsync(cursor, 0, N_NODES * sizeof(int), 0);
    csr_fill_kernel<<<1184, 256>>>(src, dst, rowptr, cursor, csrc, N_EDGES);

    // Layer 1: m1 = (x * ns) @ W1 ; h = relu(agg(m1) * nd + b1)
    gemm_rowscale<128, 128, 32, 8, 8>
        <<<(N_NODES + 127) / 128, 256>>>(x, ns, W1, m1, N_NODES, IN_F);
    aggregate128<true><<<(N_NODES * 32 + 255) / 256, 256>>>(
        m1, rowptr, din, csrc, nd, b1, h, N_NODES);

    // Layer 2: m2 = (h * ns) @ W2 ; out = agg(m2) * nd + b2
    gemm_rowscale<128, 64, 32, 8, 4>
        <<<(N_NODES + 127) / 128, 256>>>(h, ns, W2, m2, N_NODES, HID);
    aggregate64<false><<<(N_NODES * 32 + 255) / 256, 256>>>(
        m2, rowptr, din, csrc, nd, b2, out, N_NODES);
}

// round 9
// speedup vs baseline: 1.1572x; 1.1572x over previous
#include <cuda_runtime.h>
#include <cstdint>

#define N_NODES 50000
#define N_EDGES 800000
#define IN_F 256
#define HID 128
#define OUTF 64

// ---------------- scratch (no allocations allowed) ----------------
__device__ int   g_deg_in[N_NODES];
__device__ int   g_deg_out[N_NODES];
__device__ int   g_rowptr[N_NODES];      // exclusive prefix of deg_in
__device__ int   g_blocktot[256];        // scan block totals
__device__ int   g_cursor[N_NODES];      // CSR fill cursors
__device__ int   g_csrc[N_EDGES];        // src node of each dst-grouped edge
__device__ float g_norm_src[N_NODES];
__device__ float g_norm_dst[N_NODES];
__device__ float g_m1[(size_t)N_NODES * HID];   // x @ W1 (unscaled)
__device__ float g_h[(size_t)N_NODES * HID];    // relu(agg1*nd + b1)
__device__ float g_m2[(size_t)N_NODES * OUTF];  // h @ W2 (unscaled)

// ---------------- degree counting ----------------
__global__ __launch_bounds__(256) void degree_kernel(
    const int* __restrict__ src, const int* __restrict__ dst,
    int* __restrict__ deg_out, int* __restrict__ deg_in, int E) {
    for (int e = blockIdx.x * blockDim.x + threadIdx.x; e < E;
         e += gridDim.x * blockDim.x) {
        atomicAdd(&deg_out[__ldg(&src[e])], 1);
        atomicAdd(&deg_in[__ldg(&dst[e])], 1);
    }
}

__global__ __launch_bounds__(256) void norm_kernel(
    const int* __restrict__ dout, const int* __restrict__ din,
    float* __restrict__ ns, float* __restrict__ nd, int n) {
    int i = blockIdx.x * blockDim.x + threadIdx.x;
    if (i < n) {
        ns[i] = rsqrtf((float)max(dout[i], 1));
        nd[i] = rsqrtf((float)max(din[i], 1));
    }
}

// ---------------- 3-phase exclusive scan over deg_in -> rowptr ----------------
__global__ __launch_bounds__(256) void scan_phase1(
    const int* __restrict__ deg, int* __restrict__ excl,
    int* __restrict__ btot, int n) {
    __shared__ int sm[256];
    int i = blockIdx.x * 256 + threadIdx.x;
    int v = (i < n) ? deg[i] : 0;
    sm[threadIdx.x] = v;
    __syncthreads();
#pragma unroll
    for (int off = 1; off < 256; off <<= 1) {
        int t = (threadIdx.x >= off) ? sm[threadIdx.x - off] : 0;
        __syncthreads();
        sm[threadIdx.x] += t;
        __syncthreads();
    }
    if (i < n) excl[i] = sm[threadIdx.x] - v;
    if (threadIdx.x == 255) btot[blockIdx.x] = sm[255];
}

__global__ __launch_bounds__(256) void scan_phase2(int* __restrict__ btot, int nb) {
    __shared__ int sm[256];
    int v = (threadIdx.x < nb) ? btot[threadIdx.x] : 0;
    sm[threadIdx.x] = v;
    __syncthreads();
#pragma unroll
    for (int off = 1; off < 256; off <<= 1) {
        int t = (threadIdx.x >= off) ? sm[threadIdx.x - off] : 0;
        __syncthreads();
        sm[threadIdx.x] += t;
        __syncthreads();
    }
    if (threadIdx.x < nb) btot[threadIdx.x] = sm[threadIdx.x] - v;
}

__global__ __launch_bounds__(256) void scan_phase3(
    int* __restrict__ excl, const int* __restrict__ btot, int n) {
    int i = blockIdx.x * 256 + threadIdx.x;
    if (i < n) excl[i] += btot[blockIdx.x];
}

// ---------------- CSR fill: group edge srcs by dst ----------------
__global__ __launch_bounds__(256) void csr_fill_kernel(
    const int* __restrict__ src, const int* __restrict__ dst,
    const int* __restrict__ rowptr, int* __restrict__ cursor,
    int* __restrict__ csrc, int E) {
    for (int e = blockIdx.x * blockDim.x + threadIdx.x; e < E;
         e += gridDim.x * blockDim.x) {
        int d = __ldg(&dst[e]);
        int pos = __ldg(&rowptr[d]) + atomicAdd(&cursor[d], 1);
        csrc[pos] = __ldg(&src[e]);
    }
}

// ---------------- plain SGEMM: C[M,BN] = A[M,K] @ W[K,BN] ----------------
template <int BM, int BN, int BK, int TM, int TN>
__global__ __launch_bounds__(256) void gemm_plain(
    const float* __restrict__ A, const float* __restrict__ W,
    float* __restrict__ C, int M, int K) {
    __shared__ float As[BK][BM + 4];
    __shared__ float Ws[BK][BN];

    const int tid = threadIdx.x;
    const int row0 = blockIdx.x * BM;
    constexpr int TX = BN / TN;
    const int tx = tid % TX;
    const int ty = tid / TX;

    float acc[TM][TN];
#pragma unroll
    for (int i = 0; i < TM; i++)
#pragma unroll
        for (int j = 0; j < TN; j++) acc[i][j] = 0.0f;

    constexpr int A_F4 = (BM * BK / 4) / 256;
    constexpr int W_F4 = (BK * BN / 4) / 256;
    constexpr int KC4 = BK / 4;
    constexpr int NC4 = BN / 4;

    for (int k0 = 0; k0 < K; k0 += BK) {
        __syncthreads();
#pragma unroll
        for (int i = 0; i < A_F4; i++) {
            int idx = tid + i * 256;
            int r = idx / KC4;
            int c4 = idx % KC4;
            int grow = row0 + r;
            float4 v = make_float4(0.f, 0.f, 0.f, 0.f);
            if (grow < M)
                v = __ldg((const float4*)(A + (size_t)grow * K + k0 + c4 * 4));
            As[c4 * 4 + 0][r] = v.x;
            As[c4 * 4 + 1][r] = v.y;
            As[c4 * 4 + 2][r] = v.z;
            As[c4 * 4 + 3][r] = v.w;
        }
#pragma unroll
        for (int i = 0; i < W_F4; i++) {
            int idx = tid + i * 256;
            int kk = idx / NC4;
            int n4 = idx % NC4;
            float4 v = __ldg((const float4*)(W + (size_t)(k0 + kk) * BN + n4 * 4));
            *(float4*)&Ws[kk][n4 * 4] = v;
        }
        __syncthreads();
#pragma unroll
        for (int k = 0; k < BK; k++) {
            float a[TM], b[TN];
#pragma unroll
            for (int i = 0; i < TM; i += 4) {
                float4 t = *(const float4*)&As[k][ty * TM + i];
                a[i] = t.x; a[i + 1] = t.y; a[i + 2] = t.z; a[i + 3] = t.w;
            }
#pragma unroll
            for (int j = 0; j < TN; j += 4) {
                float4 t = *(const float4*)&Ws[k][tx * TN + j];
                b[j] = t.x; b[j + 1] = t.y; b[j + 2] = t.z; b[j + 3] = t.w;
            }
#pragma unroll
            for (int i = 0; i < TM; i++)
#pragma unroll
                for (int j = 0; j < TN; j++) acc[i][j] += a[i] * b[j];
        }
    }
#pragma unroll
    for (int i = 0; i < TM; i++) {
        int grow = row0 + ty * TM + i;
        if (grow < M) {
#pragma unroll
            for (int j = 0; j < TN; j += 4) {
                float4 v = make_float4(acc[i][j], acc[i][j + 1], acc[i][j + 2], acc[i][j + 3]);
                *(float4*)(C + (size_t)grow * BN + tx * TN + j) = v;
            }
        }
    }
}

// ---------------- gather aggregation with src-scale, fused epilogue ----------------
// out[n] = (RELU?)( (sum_{e in in(n)} ns[src_e] * m[src_e]) * nd[n] + bias )
// (ns folded here: ((h.*ns)@W)[s,:] == ns[s]*(h@W)[s,:])
template <bool RELU>
__global__ __launch_bounds__(256) void aggregate128(
    const float* __restrict__ m, const int* __restrict__ rowptr,
    const int* __restrict__ deg, const int* __restrict__ csrc,
    const float* __restrict__ ns, const float* __restrict__ nd,
    const float* __restrict__ bias, float* __restrict__ out, int N) {
    int warp = (blockIdx.x * blockDim.x + threadIdx.x) >> 5;
    int lane = threadIdx.x & 31;
    if (warp >= N) return;
    int start = __ldg(&rowptr[warp]);
    int cnt = __ldg(&deg[warp]);
    float4 acc0 = make_float4(0.f, 0.f, 0.f, 0.f);
    float4 acc1 = make_float4(0.f, 0.f, 0.f, 0.f);
    int j = 0;
    for (; j + 2 <= cnt; j += 2) {
        int s0 = __ldg(&csrc[start + j]);
        int s1 = __ldg(&csrc[start + j + 1]);
        float c0 = __ldg(&ns[s0]);
        float c1 = __ldg(&ns[s1]);
        float4 v0 = __ldg((const float4*)(m + (size_t)s0 * 128 + lane * 4));
        float4 v1 = __ldg((const float4*)(m + (size_t)s1 * 128 + lane * 4));
        acc0.x += v0.x * c0; acc0.y += v0.y * c0; acc0.z += v0.z * c0; acc0.w += v0.w * c0;
        acc1.x += v1.x * c1; acc1.y += v1.y * c1; acc1.z += v1.z * c1; acc1.w += v1.w * c1;
    }
    if (j < cnt) {
        int s0 = __ldg(&csrc[start + j]);
        float c0 = __ldg(&ns[s0]);
        float4 v0 = __ldg((const float4*)(m + (size_t)s0 * 128 + lane * 4));
        acc0.x += v0.x * c0; acc0.y += v0.y * c0; acc0.z += v0.z * c0; acc0.w += v0.w * c0;
    }
    float n = __ldg(&nd[warp]);
    float4 b = __ldg((const float4*)(bias + lane * 4));
    float4 r;
    r.x = (acc0.x + acc1.x) * n + b.x;
    r.y = (acc0.y + acc1.y) * n + b.y;
    r.z = (acc0.z + acc1.z) * n + b.z;
    r.w = (acc0.w + acc1.w) * n + b.w;
    if (RELU) {
        r.x = fmaxf(r.x, 0.f); r.y = fmaxf(r.y, 0.f);
        r.z = fmaxf(r.z, 0.f); r.w = fmaxf(r.w, 0.f);
    }
    *(float4*)(out + (size_t)warp * 128 + lane * 4) = r;
}

template <bool RELU>
__global__ __launch_bounds__(256) void aggregate64(
    const float* __restrict__ m, const int* __restrict__ rowptr,
    const int* __restrict__ deg, const int* __restrict__ csrc,
    const float* __restrict__ ns, const float* __restrict__ nd,
    const float* __restrict__ bias, float* __restrict__ out, int N) {
    int warp = (blockIdx.x * blockDim.x + threadIdx.x) >> 5;
    int lane = threadIdx.x & 31;
    if (warp >= N) return;
    int start = __ldg(&rowptr[warp]);
    int cnt = __ldg(&deg[warp]);
    float2 acc0 = make_float2(0.f, 0.f);
    float2 acc1 = make_float2(0.f, 0.f);
    int j = 0;
    for (; j + 2 <= cnt; j += 2) {
        int s0 = __ldg(&csrc[start + j]);
        int s1 = __ldg(&csrc[start + j + 1]);
        float c0 = __ldg(&ns[s0]);
        float c1 = __ldg(&ns[s1]);
        float2 v0 = __ldg((const float2*)(m + (size_t)s0 * 64 + lane * 2));
        float2 v1 = __ldg((const float2*)(m + (size_t)s1 * 64 + lane * 2));
        acc0.x += v0.x * c0; acc0.y += v0.y * c0;
        acc1.x += v1.x * c1; acc1.y += v1.y * c1;
    }
    if (j < cnt) {
        int s0 = __ldg(&csrc[start + j]);
        float c0 = __ldg(&ns[s0]);
        float2 v0 = __ldg((const float2*)(m + (size_t)s0 * 64 + lane * 2));
        acc0.x += v0.x * c0; acc0.y += v0.y * c0;
    }
    float n = __ldg(&nd[warp]);
    float2 b = __ldg((const float2*)(bias + lane * 2));
    float2 r;
    r.x = (acc0.x + acc1.x) * n + b.x;
    r.y = (acc0.y + acc1.y) * n + b.y;
    if (RELU) { r.x = fmaxf(r.x, 0.f); r.y = fmaxf(r.y, 0.f); }
    *(float2*)(out + (size_t)warp * 64 + lane * 2) = r;
}

// ---------------- launch ----------------
extern "C" void kernel_launch(void* const* d_in, const int* in_sizes, int n_in,
                              void* d_out, int out_size) {
    const float* x = (const float*)d_in[0];
    const int* src = (const int*)d_in[1];   // int32 (JAX x64 disabled)
    const int* dst = (const int*)d_in[2];
    const float* W1 = (const float*)d_in[3];
    const float* b1 = (const float*)d_in[4];
    const float* W2 = (const float*)d_in[5];
    const float* b2 = (const float*)d_in[6];
    float* out = (float*)d_out;

    int *din, *dout_, *rowptr, *btot, *cursor, *csrc;
    float *ns, *nd, *m1, *h, *m2;
    cudaGetSymbolAddress((void**)&din, g_deg_in);
    cudaGetSymbolAddress((void**)&dout_, g_deg_out);
    cudaGetSymbolAddress((void**)&rowptr, g_rowptr);
    cudaGetSymbolAddress((void**)&btot, g_blocktot);
    cudaGetSymbolAddress((void**)&cursor, g_cursor);
    cudaGetSymbolAddress((void**)&csrc, g_csrc);
    cudaGetSymbolAddress((void**)&ns, g_norm_src);
    cudaGetSymbolAddress((void**)&nd, g_norm_dst);
    cudaGetSymbolAddress((void**)&m1, g_m1);
    cudaGetSymbolAddress((void**)&h, g_h);
    cudaGetSymbolAddress((void**)&m2, g_m2);

    const int NB = (N_NODES + 255) / 256;   // 196

    // Fork: preprocessing runs on a side stream, concurrent with GEMM1.
    // (Streams/events are created fresh per call and never destroyed —
    //  kernel_launch is invoked only a handful of times; no device memory involved.)
    cudaStream_t sp;
    cudaStreamCreateWithFlags(&sp, cudaStreamNonBlocking);
    cudaEvent_t e_fork, e_join;
    cudaEventCreateWithFlags(&e_fork, cudaEventDisableTiming);
    cudaEventCreateWithFlags(&e_join, cudaEventDisableTiming);

    cudaEventRecord(e_fork, 0);
    cudaStreamWaitEvent(sp, e_fork, 0);

    // --- side stream: degrees -> norms -> scan -> CSR fill ---
    cudaMemsetAsync(din, 0, N_NODES * sizeof(int), sp);
    cudaMemsetAsync(dout_, 0, N_NODES * sizeof(int), sp);
    cudaMemsetAsync(cursor, 0, N_NODES * sizeof(int), sp);
    degree_kernel<<<1184, 256, 0, sp>>>(src, dst, dout_, din, N_EDGES);
    norm_kernel<<<NB, 256, 0, sp>>>(dout_, din, ns, nd, N_NODES);
    scan_phase1<<<NB, 256, 0, sp>>>(din, rowptr, btot, N_NODES);
    scan_phase2<<<1, 256, 0, sp>>>(btot, NB);
    scan_phase3<<<NB, 256, 0, sp>>>(rowptr, btot, N_NODES);
    csr_fill_kernel<<<1184, 256, 0, sp>>>(src, dst, rowptr, cursor, csrc, N_EDGES);
    cudaEventRecord(e_join, sp);

    // --- main stream: GEMM1 (plain, no dependencies) ---
    gemm_plain<128, 128, 32, 8, 8>
        <<<(N_NODES + 127) / 128, 256>>>(x, W1, m1, N_NODES, IN_F);

    // join: aggregation needs CSR + norms
    cudaStreamWaitEvent(0, e_join, 0);

    // h = relu( (sum ns[s]*m1[s]) * nd + b1 )
    aggregate128<true><<<(N_NODES * 32 + 255) / 256, 256>>>(
        m1, rowptr, din, csrc, ns, nd, b1, h, N_NODES);

    // Layer 2: m2 = h @ W2 ; out = (sum ns[s]*m2[s]) * nd + b2
    gemm_plain<128, 64, 32, 8, 4>
        <<<(N_NODES + 127) / 128, 256>>>(h, W2, m2, N_NODES, HID);
    aggregate64<false><<<(N_NODES * 32 + 255) / 256, 256>>>(
        m2, rowptr, din, csrc, ns, nd, b2, out, N_NODES);
}

// round 12
// speedup vs baseline: 1.3440x; 1.1614x over previous
#include <cuda_runtime.h>
#include <cstdint>

#define N_NODES 50000
#define N_EDGES 800000
#define IN_F 256
#define HID 128
#define OUTF 64

// ---------------- scratch (no allocations allowed) ----------------
__device__ int   g_deg_in[N_NODES];
__device__ int   g_deg_out[N_NODES];
__device__ int   g_rowptr[N_NODES];
__device__ int   g_blocktot[256];
__device__ int   g_cursor[N_NODES];
__device__ int   g_csrc[N_EDGES];
__device__ float g_norm_src[N_NODES];
__device__ float g_norm_dst[N_NODES];
__device__ float g_m1[(size_t)N_NODES * HID];   // x @ W1 (unscaled)
__device__ float g_h[(size_t)N_NODES * HID];    // relu(agg1*nd + b1)
__device__ float g_m2[(size_t)N_NODES * OUTF];  // h @ W2 (unscaled)

// ---------------- degree counting ----------------
__global__ __launch_bounds__(256) void degree_kernel(
    const int* __restrict__ src, const int* __restrict__ dst,
    int* __restrict__ deg_out, int* __restrict__ deg_in, int E) {
    for (int e = blockIdx.x * blockDim.x + threadIdx.x; e < E;
         e += gridDim.x * blockDim.x) {
        atomicAdd(&deg_out[__ldg(&src[e])], 1);
        atomicAdd(&deg_in[__ldg(&dst[e])], 1);
    }
}

__global__ __launch_bounds__(256) void norm_kernel(
    const int* __restrict__ dout, const int* __restrict__ din,
    float* __restrict__ ns, float* __restrict__ nd, int n) {
    int i = blockIdx.x * blockDim.x + threadIdx.x;
    if (i < n) {
        ns[i] = rsqrtf((float)max(dout[i], 1));
        nd[i] = rsqrtf((float)max(din[i], 1));
    }
}

// ---------------- 3-phase exclusive scan ----------------
__global__ __launch_bounds__(256) void scan_phase1(
    const int* __restrict__ deg, int* __restrict__ excl,
    int* __restrict__ btot, int n) {
    __shared__ int sm[256];
    int i = blockIdx.x * 256 + threadIdx.x;
    int v = (i < n) ? deg[i] : 0;
    sm[threadIdx.x] = v;
    __syncthreads();
#pragma unroll
    for (int off = 1; off < 256; off <<= 1) {
        int t = (threadIdx.x >= off) ? sm[threadIdx.x - off] : 0;
        __syncthreads();
        sm[threadIdx.x] += t;
        __syncthreads();
    }
    if (i < n) excl[i] = sm[threadIdx.x] - v;
    if (threadIdx.x == 255) btot[blockIdx.x] = sm[255];
}

__global__ __launch_bounds__(256) void scan_phase2(int* __restrict__ btot, int nb) {
    __shared__ int sm[256];
    int v = (threadIdx.x < nb) ? btot[threadIdx.x] : 0;
    sm[threadIdx.x] = v;
    __syncthreads();
#pragma unroll
    for (int off = 1; off < 256; off <<= 1) {
        int t = (threadIdx.x >= off) ? sm[threadIdx.x - off] : 0;
        __syncthreads();
        sm[threadIdx.x] += t;
        __syncthreads();
    }
    if (threadIdx.x < nb) btot[threadIdx.x] = sm[threadIdx.x] - v;
}

__global__ __launch_bounds__(256) void scan_phase3(
    int* __restrict__ excl, const int* __restrict__ btot, int n) {
    int i = blockIdx.x * 256 + threadIdx.x;
    if (i < n) excl[i] += btot[blockIdx.x];
}

// ---------------- CSR fill ----------------
__global__ __launch_bounds__(256) void csr_fill_kernel(
    const int* __restrict__ src, const int* __restrict__ dst,
    const int* __restrict__ rowptr, int* __restrict__ cursor,
    int* __restrict__ csrc, int E) {
    for (int e = blockIdx.x * blockDim.x + threadIdx.x; e < E;
         e += gridDim.x * blockDim.x) {
        int d = __ldg(&dst[e]);
        int pos = __ldg(&rowptr[d]) + atomicAdd(&cursor[d], 1);
        csrc[pos] = __ldg(&src[e]);
    }
}

// ---------------- tf32 helpers ----------------
__device__ __forceinline__ float to_tf32(float x) {
    uint32_t u;
    asm("cvt.rna.tf32.f32 %0, %1;" : "=r"(u) : "f"(x));
    return __uint_as_float(u);
}

__device__ __forceinline__ void mma_tf32(float* d, const float* a, float b0, float b1) {
    asm volatile(
        "mma.sync.aligned.m16n8k8.row.col.f32.tf32.tf32.f32 "
        "{%0,%1,%2,%3}, {%4,%5,%6,%7}, {%8,%9}, {%0,%1,%2,%3};"
        : "+f"(d[0]), "+f"(d[1]), "+f"(d[2]), "+f"(d[3])
        : "r"(__float_as_uint(a[0])), "r"(__float_as_uint(a[1])),
          "r"(__float_as_uint(a[2])), "r"(__float_as_uint(a[3])),
          "r"(__float_as_uint(b0)), "r"(__float_as_uint(b1)));
}

// ---------------- tf32 tensor GEMM: C[M,BN] = A[M,K] @ W[K,BN] ----------------
// 256 threads = 8 warps in 4(m) x 2(n); warp tile 32 x (BN/2); atoms m16n8k8.
template <int BM, int BN, int BK>
__global__ __launch_bounds__(256) void gemm_tf32(
    const float* __restrict__ A, const float* __restrict__ W,
    float* __restrict__ C, int M, int K) {
    __shared__ float Am[BM][BK + 4];   // m-major A: conflict-free fragment loads
    __shared__ float Ws[BK][BN + 4];   // k-major W

    const int tid = threadIdx.x;
    const int wid = tid >> 5, lane = tid & 31;
    const int wm = wid & 3, wn = wid >> 2;
    const int g = lane >> 2, tig = lane & 3;
    const int row0 = blockIdx.x * BM;

    constexpr int WN = BN / 2;    // warp n-extent
    constexpr int NA = WN / 8;    // n-atoms per warp
    constexpr int A_F4 = BM * (BK / 4) / 256;
    constexpr int W_F4 = BK * (BN / 4) / 256;

    float acc[2][NA][4];
#pragma unroll
    for (int i = 0; i < 2; i++)
#pragma unroll
        for (int j = 0; j < NA; j++)
#pragma unroll
            for (int q = 0; q < 4; q++) acc[i][j][q] = 0.0f;

    for (int k0 = 0; k0 < K; k0 += BK) {
        __syncthreads();
#pragma unroll
        for (int i = 0; i < A_F4; i++) {
            int idx = tid + i * 256;
            int r = idx >> 3;            // / (BK/4) == 8
            int c4 = (idx & 7) * 4;
            float4 v = make_float4(0.f, 0.f, 0.f, 0.f);
            if (row0 + r < M)
                v = __ldg((const float4*)(A + (size_t)(row0 + r) * K + k0 + c4));
            Am[r][c4 + 0] = to_tf32(v.x);
            Am[r][c4 + 1] = to_tf32(v.y);
            Am[r][c4 + 2] = to_tf32(v.z);
            Am[r][c4 + 3] = to_tf32(v.w);
        }
#pragma unroll
        for (int i = 0; i < W_F4; i++) {
            int idx = tid + i * 256;
            int kk = idx / (BN / 4);
            int n4 = (idx % (BN / 4)) * 4;
            float4 v = __ldg((const float4*)(W + (size_t)(k0 + kk) * BN + n4));
            Ws[kk][n4 + 0] = to_tf32(v.x);
            Ws[kk][n4 + 1] = to_tf32(v.y);
            Ws[kk][n4 + 2] = to_tf32(v.z);
            Ws[kk][n4 + 3] = to_tf32(v.w);
        }
        __syncthreads();
#pragma unroll
        for (int ks = 0; ks < BK / 8; ks++) {
            int kb = ks * 8;
            float a[2][4];
#pragma unroll
            for (int ma = 0; ma < 2; ma++) {
                int r = wm * 32 + ma * 16;
                a[ma][0] = Am[r + g][kb + tig];
                a[ma][1] = Am[r + g + 8][kb + tig];
                a[ma][2] = Am[r + g][kb + tig + 4];
                a[ma][3] = Am[r + g + 8][kb + tig + 4];
            }
#pragma unroll
            for (int na = 0; na < NA; na++) {
                int c = wn * WN + na * 8;
                float b0 = Ws[kb + tig][c + g];
                float b1 = Ws[kb + tig + 4][c + g];
                mma_tf32(acc[0][na], a[0], b0, b1);
                mma_tf32(acc[1][na], a[1], b0, b1);
            }
        }
    }
    // store (C row length == BN)
#pragma unroll
    for (int ma = 0; ma < 2; ma++) {
        int r0g = row0 + wm * 32 + ma * 16 + g;
#pragma unroll
        for (int na = 0; na < NA; na++) {
            int c = wn * WN + na * 8 + 2 * tig;
            if (r0g < M)
                *(float2*)(C + (size_t)r0g * BN + c) =
                    make_float2(acc[ma][na][0], acc[ma][na][1]);
            if (r0g + 8 < M)
                *(float2*)(C + (size_t)(r0g + 8) * BN + c) =
                    make_float2(acc[ma][na][2], acc[ma][na][3]);
        }
    }
}

// ---------------- gather aggregation with src-scale, fused epilogue ----------------
template <bool RELU>
__global__ __launch_bounds__(256) void aggregate128(
    const float* __restrict__ m, const int* __restrict__ rowptr,
    const int* __restrict__ deg, const int* __restrict__ csrc,
    const float* __restrict__ ns, const float* __restrict__ nd,
    const float* __restrict__ bias, float* __restrict__ out, int N) {
    int warp = (blockIdx.x * blockDim.x + threadIdx.x) >> 5;
    int lane = threadIdx.x & 31;
    if (warp >= N) return;
    int start = __ldg(&rowptr[warp]);
    int cnt = __ldg(&deg[warp]);
    float4 acc0 = make_float4(0.f, 0.f, 0.f, 0.f);
    float4 acc1 = make_float4(0.f, 0.f, 0.f, 0.f);
    int j = 0;
    for (; j + 2 <= cnt; j += 2) {
        int s0 = __ldg(&csrc[start + j]);
        int s1 = __ldg(&csrc[start + j + 1]);
        float c0 = __ldg(&ns[s0]);
        float c1 = __ldg(&ns[s1]);
        float4 v0 = __ldg((const float4*)(m + (size_t)s0 * 128 + lane * 4));
        float4 v1 = __ldg((const float4*)(m + (size_t)s1 * 128 + lane * 4));
        acc0.x += v0.x * c0; acc0.y += v0.y * c0; acc0.z += v0.z * c0; acc0.w += v0.w * c0;
        acc1.x += v1.x * c1; acc1.y += v1.y * c1; acc1.z += v1.z * c1; acc1.w += v1.w * c1;
    }
    if (j < cnt) {
        int s0 = __ldg(&csrc[start + j]);
        float c0 = __ldg(&ns[s0]);
        float4 v0 = __ldg((const float4*)(m + (size_t)s0 * 128 + lane * 4));
        acc0.x += v0.x * c0; acc0.y += v0.y * c0; acc0.z += v0.z * c0; acc0.w += v0.w * c0;
    }
    float n = __ldg(&nd[warp]);
    float4 b = __ldg((const float4*)(bias + lane * 4));
    float4 r;
    r.x = (acc0.x + acc1.x) * n + b.x;
    r.y = (acc0.y + acc1.y) * n + b.y;
    r.z = (acc0.z + acc1.z) * n + b.z;
    r.w = (acc0.w + acc1.w) * n + b.w;
    if (RELU) {
        r.x = fmaxf(r.x, 0.f); r.y = fmaxf(r.y, 0.f);
        r.z = fmaxf(r.z, 0.f); r.w = fmaxf(r.w, 0.f);
    }
    *(float4*)(out + (size_t)warp * 128 + lane * 4) = r;
}

template <bool RELU>
__global__ __launch_bounds__(256) void aggregate64(
    const float* __restrict__ m, const int* __restrict__ rowptr,
    const int* __restrict__ deg, const int* __restrict__ csrc,
    const float* __restrict__ ns, const float* __restrict__ nd,
    const float* __restrict__ bias, float* __restrict__ out, int N) {
    int warp = (blockIdx.x * blockDim.x + threadIdx.x) >> 5;
    int lane = threadIdx.x & 31;
    if (warp >= N) return;
    int start = __ldg(&rowptr[warp]);
    int cnt = __ldg(&deg[warp]);
    float2 acc0 = make_float2(0.f, 0.f);
    float2 acc1 = make_float2(0.f, 0.f);
    int j = 0;
    for (; j + 2 <= cnt; j += 2) {
        int s0 = __ldg(&csrc[start + j]);
        int s1 = __ldg(&csrc[start + j + 1]);
        float c0 = __ldg(&ns[s0]);
        float c1 = __ldg(&ns[s1]);
        float2 v0 = __ldg((const float2*)(m + (size_t)s0 * 64 + lane * 2));
        float2 v1 = __ldg((const float2*)(m + (size_t)s1 * 64 + lane * 2));
        acc0.x += v0.x * c0; acc0.y += v0.y * c0;
        acc1.x += v1.x * c1; acc1.y += v1.y * c1;
    }
    if (j < cnt) {
        int s0 = __ldg(&csrc[start + j]);
        float c0 = __ldg(&ns[s0]);
        float2 v0 = __ldg((const float2*)(m + (size_t)s0 * 64 + lane * 2));
        acc0.x += v0.x * c0; acc0.y += v0.y * c0;
    }
    float n = __ldg(&nd[warp]);
    float2 b = __ldg((const float2*)(bias + lane * 2));
    float2 r;
    r.x = (acc0.x + acc1.x) * n + b.x;
    r.y = (acc0.y + acc1.y) * n + b.y;
    if (RELU) { r.x = fmaxf(r.x, 0.f); r.y = fmaxf(r.y, 0.f); }
    *(float2*)(out + (size_t)warp * 64 + lane * 2) = r;
}

// ---------------- launch ----------------
extern "C" void kernel_launch(void* const* d_in, const int* in_sizes, int n_in,
                              void* d_out, int out_size) {
    const float* x = (const float*)d_in[0];
    const int* src = (const int*)d_in[1];   // int32 (JAX x64 disabled)
    const int* dst = (const int*)d_in[2];
    const float* W1 = (const float*)d_in[3];
    const float* b1 = (const float*)d_in[4];
    const float* W2 = (const float*)d_in[5];
    const float* b2 = (const float*)d_in[6];
    float* out = (float*)d_out;

    int *din, *dout_, *rowptr, *btot, *cursor, *csrc;
    float *ns, *nd, *m1, *h, *m2;
    cudaGetSymbolAddress((void**)&din, g_deg_in);
    cudaGetSymbolAddress((void**)&dout_, g_deg_out);
    cudaGetSymbolAddress((void**)&rowptr, g_rowptr);
    cudaGetSymbolAddress((void**)&btot, g_blocktot);
    cudaGetSymbolAddress((void**)&cursor, g_cursor);
    cudaGetSymbolAddress((void**)&csrc, g_csrc);
    cudaGetSymbolAddress((void**)&ns, g_norm_src);
    cudaGetSymbolAddress((void**)&nd, g_norm_dst);
    cudaGetSymbolAddress((void**)&m1, g_m1);
    cudaGetSymbolAddress((void**)&h, g_h);
    cudaGetSymbolAddress((void**)&m2, g_m2);

    const int NB = (N_NODES + 255) / 256;   // 196

    // Fork: preprocessing on side stream, concurrent with GEMM1.
    cudaStream_t sp;
    cudaStreamCreateWithFlags(&sp, cudaStreamNonBlocking);
    cudaEvent_t e_fork, e_join;
    cudaEventCreateWithFlags(&e_fork, cudaEventDisableTiming);
    cudaEventCreateWithFlags(&e_join, cudaEventDisableTiming);

    cudaEventRecord(e_fork, 0);
    cudaStreamWaitEvent(sp, e_fork, 0);

    cudaMemsetAsync(din, 0, N_NODES * sizeof(int), sp);
    cudaMemsetAsync(dout_, 0, N_NODES * sizeof(int), sp);
    cudaMemsetAsync(cursor, 0, N_NODES * sizeof(int), sp);
    degree_kernel<<<1184, 256, 0, sp>>>(src, dst, dout_, din, N_EDGES);
    norm_kernel<<<NB, 256, 0, sp>>>(dout_, din, ns, nd, N_NODES);
    scan_phase1<<<NB, 256, 0, sp>>>(din, rowptr, btot, N_NODES);
    scan_phase2<<<1, 256, 0, sp>>>(btot, NB);
    scan_phase3<<<NB, 256, 0, sp>>>(rowptr, btot, N_NODES);
    csr_fill_kernel<<<1184, 256, 0, sp>>>(src, dst, rowptr, cursor, csrc, N_EDGES);
    cudaEventRecord(e_join, sp);

    // main stream: GEMM1 (tf32 tensor)
    gemm_tf32<128, 128, 32>
        <<<(N_NODES + 127) / 128, 256>>>(x, W1, m1, N_NODES, IN_F);

    cudaStreamWaitEvent(0, e_join, 0);

    aggregate128<true><<<(N_NODES * 32 + 255) / 256, 256>>>(
        m1, rowptr, din, csrc, ns, nd, b1, h, N_NODES);

    gemm_tf32<128, 64, 32>
        <<<(N_NODES + 127) / 128, 256>>>(h, W2, m2, N_NODES, HID);
    aggregate64<false><<<(N_NODES * 32 + 255) / 256, 256>>>(
        m2, rowptr, din, csrc, ns, nd, b2, out, N_NODES);
}